// round 2
// baseline (speedup 1.0000x reference)
#include <cuda_runtime.h>
#include <cuda_bf16.h>
#include <cstdint>

// ============================================================================
// LogMM: out[16384,1024] = log( x[16384,1024] @ matrix[1024,1024] )
// (reference's big/small branches sum to exactly log(max(y,tiny)))
//
// The harness's virtual arch is compute_103 (no 'a'), so tcgen05 is only
// emitted when the FEAT macro says the 'a' feature set exists; otherwise we
// compile a baseline-ISA bf16 mma.sync (HMMA) pipeline that is legal on
// plain sm_103. Both paths: 128x128 tile, BK=64, double-buffered SMEM,
// fused __logf epilogue.
// ============================================================================

#define M_TOTAL 16384
#define N_TOTAL 1024
#define K_TOTAL 1024
#define TILE_M 128
#define TILE_N 128
#define BK 64                    // bf16 per K-chunk (128 bytes per row)
#define NCHUNK (K_TOTAL / BK)    // 16

#if defined(__CUDA_ARCH__) && (defined(__CUDA_ARCH_FEAT_SM103_ALL) || defined(__CUDA_ARCH_FEAT_SM100_ALL))
#define HAS_TCGEN05 1
#else
#define HAS_TCGEN05 0
#endif

// SMEM layout (dynamic):
//   [0]      tmem ptr (tcgen05 path only)
//   [8]      mbar buf0   [16] mbar buf1
//   [1024]   A0 (128x128B = 16KB), B0, A1, B1
static constexpr int SMEM_TMEM  = 0;
static constexpr int SMEM_MBAR0 = 8;
static constexpr int SMEM_MBAR1 = 16;
static constexpr int SMEM_TILES = 1024;
static constexpr int TILE_BYTES = TILE_M * 128;     // 16384
static constexpr int BUF_STRIDE = 2 * TILE_BYTES;   // A+B per buffer
static constexpr int SMEM_TOTAL = SMEM_TILES + 2 * BUF_STRIDE;  // 66560

static constexpr int TMEM_COLS = 128;

// Scratch bf16 buffers (device globals: allocation-free)
__device__ __align__(256) __nv_bfloat16 g_xb[(size_t)M_TOTAL * K_TOTAL];
__device__ __align__(256) __nv_bfloat16 g_bt[(size_t)N_TOTAL * K_TOTAL];

// ---------------------------------------------------------------------------
// Common helpers
// ---------------------------------------------------------------------------
__device__ __forceinline__ uint32_t smem_u32(const void* p) {
    uint32_t a;
    asm("{ .reg .u64 t; cvta.to.shared.u64 t, %1; cvt.u32.u64 %0, t; }" : "=r"(a) : "l"(p));
    return a;
}
__device__ __forceinline__ uint32_t sw128(uint32_t off) {
    return off ^ ((off >> 3) & 0x70);
}

// ---------------------------------------------------------------------------
// Conversion kernels (baseline ISA)
// ---------------------------------------------------------------------------
__device__ __forceinline__ uint32_t pack_bf16x2(float a, float b) {
    __nv_bfloat162 h = __floats2bfloat162_rn(a, b);
    return *reinterpret_cast<uint32_t*>(&h);
}

__global__ void cvt_x_kernel(const float* __restrict__ x) {
    size_t i = ((size_t)blockIdx.x * blockDim.x + threadIdx.x) * 8;
    float4 a = *reinterpret_cast<const float4*>(x + i);
    float4 b = *reinterpret_cast<const float4*>(x + i + 4);
    uint4 o;
    o.x = pack_bf16x2(a.x, a.y);
    o.y = pack_bf16x2(a.z, a.w);
    o.z = pack_bf16x2(b.x, b.y);
    o.w = pack_bf16x2(b.z, b.w);
    *reinterpret_cast<uint4*>(g_xb + i) = o;
}

// matrix[K,N] fp32 -> g_bt[N,K] bf16 (transpose via smem tile)
__global__ void cvt_mT_kernel(const float* __restrict__ m) {
    __shared__ float tile[32][33];
    int k = blockIdx.y * 32 + threadIdx.y;
    int n = blockIdx.x * 32 + threadIdx.x;
    tile[threadIdx.y][threadIdx.x] = m[(size_t)k * N_TOTAL + n];
    __syncthreads();
    int on = blockIdx.x * 32 + threadIdx.y;
    int ok = blockIdx.y * 32 + threadIdx.x;
    g_bt[(size_t)on * K_TOTAL + ok] = __float2bfloat16_rn(tile[threadIdx.x][threadIdx.y]);
}

// ---------------------------------------------------------------------------
// tcgen05 helpers (only referenced when HAS_TCGEN05)
// ---------------------------------------------------------------------------
#if HAS_TCGEN05
static constexpr uint32_t MMA_IDESC =
    (1u << 4) | (1u << 7) | (1u << 10) | ((TILE_N / 8) << 17) | ((TILE_M / 16) << 24);

__device__ __forceinline__ uint32_t elect_one() {
    uint32_t pred;
    asm volatile("{\n\t.reg .pred p;\n\telect.sync _|p, 0xFFFFFFFF;\n\tselp.b32 %0, 1, 0, p;\n\t}"
                 : "=r"(pred));
    return pred;
}
#define TCGEN05_ALLOC(smem_addr, nCols) \
    asm volatile("tcgen05.alloc.cta_group::1.sync.aligned.shared::cta.b32 [%0], %1;" \
                 :: "r"((uint32_t)(smem_addr)), "r"((uint32_t)(nCols)) : "memory")
#define TCGEN05_DEALLOC(tmem_addr, nCols) \
    asm volatile("tcgen05.dealloc.cta_group::1.sync.aligned.b32 %0, %1;" \
                 :: "r"(tmem_addr), "r"((uint32_t)(nCols)))
#define TCGEN05_RELINQUISH() \
    asm volatile("tcgen05.relinquish_alloc_permit.cta_group::1.sync.aligned;")
#define TCGEN05_COMMIT(mbar) \
    asm volatile("tcgen05.commit.cta_group::1.mbarrier::arrive::one.shared::cluster.b64 [%0];" \
                 :: "r"((uint32_t)(mbar)) : "memory")
#define TCGEN05_FENCE_AFTER() \
    asm volatile("tcgen05.fence::after_thread_sync;" ::: "memory")
#define TCGEN05_WAIT_LD() \
    asm volatile("tcgen05.wait::ld.sync.aligned;" ::: "memory")
#define MBARRIER_INIT(mbar, cnt) \
    asm volatile("mbarrier.init.shared.b64 [%0], %1;" \
                 :: "r"((uint32_t)(mbar)), "r"((uint32_t)(cnt)) : "memory")
#define FENCE_PROXY_ASYNC() \
    asm volatile("fence.proxy.async.shared::cta;" ::: "memory")

#define MBARRIER_WAIT_PARITY(mbar_smem_addr, phase_parity) do { \
    uint32_t _mbar = (uint32_t)(mbar_smem_addr); \
    uint32_t _parity = (uint32_t)(phase_parity); \
    uint32_t _done; \
    asm volatile("{\n\t.reg .pred p;\n\t" \
        "mbarrier.try_wait.parity.acquire.cta.shared::cta.b64 p, [%1], %2;\n\t" \
        "selp.b32 %0, 1, 0, p;\n\t}" \
        : "=r"(_done) : "r"(_mbar), "r"(_parity) : "memory"); \
    if (!_done) { \
        asm volatile("{\n\t.reg .pred P1;\n\t" \
            "WAIT_LOOP_%=:\n\t" \
            "mbarrier.try_wait.parity.acquire.cta.shared::cta.b64 P1, [%0], %1, 0x989680;\n\t" \
            "@P1 bra.uni WAIT_DONE_%=;\n\t" \
            "bra.uni WAIT_LOOP_%=;\n\t" \
            "WAIT_DONE_%=:\n\t}" \
            :: "r"(_mbar), "r"(_parity) : "memory"); \
    } \
} while (0)

static constexpr uint64_t SMEM_DESC_BASE =
    (uint64_t(2) << 61) | (uint64_t(1) << 46) | (uint64_t(64) << 32) | (uint64_t(1) << 16);
__device__ __forceinline__ uint64_t make_desc(uint32_t addr) {
    return SMEM_DESC_BASE | ((uint64_t)(addr >> 4) & 0x3FFF);
}
__device__ __forceinline__ void mma_f16_ss(uint32_t d, uint64_t a_desc, uint64_t b_desc,
                                           uint32_t idesc, bool acc) {
    uint32_t en = acc ? 1u : 0u;
    uint32_t z = 0u;
    asm volatile("{\n\t.reg .pred p;\n\tsetp.ne.u32 p, %5, 0;\n\t"
                 "tcgen05.mma.cta_group::1.kind::f16 [%0], %1, %2, %3, {%4, %4, %4, %4}, p;\n\t}"
                 :: "r"(d), "l"(a_desc), "l"(b_desc), "r"(idesc), "r"(z), "r"(en)
                 : "memory");
}
__device__ __forceinline__ void sts128(uint32_t addr, uint4 v) {
    asm volatile("st.shared.v4.b32 [%0], {%1, %2, %3, %4};"
                 :: "r"(addr), "r"(v.x), "r"(v.y), "r"(v.z), "r"(v.w) : "memory");
}
#define LDTM_X32(r, addr) \
    asm volatile("tcgen05.ld.sync.aligned.32x32b.x32.b32 " \
        "{%0, %1, %2, %3, %4, %5, %6, %7, %8, %9, %10, %11, %12, %13, %14, %15, " \
        " %16, %17, %18, %19, %20, %21, %22, %23, %24, %25, %26, %27, %28, %29, %30, %31}, [%32];" \
        : "=r"((r)[0]),  "=r"((r)[1]),  "=r"((r)[2]),  "=r"((r)[3]), \
          "=r"((r)[4]),  "=r"((r)[5]),  "=r"((r)[6]),  "=r"((r)[7]), \
          "=r"((r)[8]),  "=r"((r)[9]),  "=r"((r)[10]), "=r"((r)[11]), \
          "=r"((r)[12]), "=r"((r)[13]), "=r"((r)[14]), "=r"((r)[15]), \
          "=r"((r)[16]), "=r"((r)[17]), "=r"((r)[18]), "=r"((r)[19]), \
          "=r"((r)[20]), "=r"((r)[21]), "=r"((r)[22]), "=r"((r)[23]), \
          "=r"((r)[24]), "=r"((r)[25]), "=r"((r)[26]), "=r"((r)[27]), \
          "=r"((r)[28]), "=r"((r)[29]), "=r"((r)[30]), "=r"((r)[31]) \
        : "r"(addr))

__device__ __forceinline__ void load_tiles_sts(uint32_t smem_base, int buf, int kc,
                                               int m0, int n0, int tid) {
    const uint4* Ag = reinterpret_cast<const uint4*>(g_xb + (size_t)m0 * K_TOTAL + kc * BK);
    const uint4* Bg = reinterpret_cast<const uint4*>(g_bt + (size_t)n0 * K_TOTAL + kc * BK);
    uint32_t Abase = smem_base + SMEM_TILES + buf * BUF_STRIDE;
    uint32_t Bbase = Abase + TILE_BYTES;
#pragma unroll
    for (int i = 0; i < 4; i++) {
        int cc = i * 256 + tid;
        int row = cc >> 3;
        int c16 = cc & 7;
        uint4 va = Ag[(size_t)row * (K_TOTAL / 8) + c16];
        uint4 vb = Bg[(size_t)row * (K_TOTAL / 8) + c16];
        uint32_t sw = sw128((uint32_t)(row * 128 + c16 * 16));
        sts128(Abase + sw, va);
        sts128(Bbase + sw, vb);
    }
}
#endif  // HAS_TCGEN05

// ---------------------------------------------------------------------------
// Baseline-ISA helpers (mma.sync path)
// ---------------------------------------------------------------------------
#if !HAS_TCGEN05 || !defined(__CUDA_ARCH__)
#endif

__device__ __forceinline__ void cp_async16(uint32_t smem_addr, const void* gptr) {
    asm volatile("cp.async.cg.shared.global [%0], [%1], 16;"
                 :: "r"(smem_addr), "l"(gptr) : "memory");
}
#define CP_COMMIT() asm volatile("cp.async.commit_group;" ::: "memory")
#define CP_WAIT(n)  asm volatile("cp.async.wait_group %0;" :: "n"(n) : "memory")

__device__ __forceinline__ void ldsm_x4(uint32_t* r, uint32_t addr) {
    asm volatile("ldmatrix.sync.aligned.m8n8.x4.shared.b16 {%0, %1, %2, %3}, [%4];"
                 : "=r"(r[0]), "=r"(r[1]), "=r"(r[2]), "=r"(r[3]) : "r"(addr));
}
__device__ __forceinline__ void mma16816(float* c, const uint32_t* a, const uint32_t* b) {
    asm volatile("mma.sync.aligned.m16n8k16.row.col.f32.bf16.bf16.f32 "
                 "{%0, %1, %2, %3}, {%4, %5, %6, %7}, {%8, %9}, {%0, %1, %2, %3};"
                 : "+f"(c[0]), "+f"(c[1]), "+f"(c[2]), "+f"(c[3])
                 : "r"(a[0]), "r"(a[1]), "r"(a[2]), "r"(a[3]), "r"(b[0]), "r"(b[1]));
}

__device__ __forceinline__ void load_tiles_async(uint32_t smem_base, int buf, int kc,
                                                 int m0, int n0, int tid) {
    const uint4* Ag = reinterpret_cast<const uint4*>(g_xb + (size_t)m0 * K_TOTAL + kc * BK);
    const uint4* Bg = reinterpret_cast<const uint4*>(g_bt + (size_t)n0 * K_TOTAL + kc * BK);
    uint32_t Abase = smem_base + SMEM_TILES + buf * BUF_STRIDE;
    uint32_t Bbase = Abase + TILE_BYTES;
#pragma unroll
    for (int i = 0; i < 4; i++) {
        int cc = i * 256 + tid;           // 1024 16B-chunks per tile
        int row = cc >> 3;                // 0..127
        int c16 = cc & 7;                 // 16B chunk within 128B row
        uint32_t sw = sw128((uint32_t)(row * 128 + c16 * 16));
        cp_async16(Abase + sw, Ag + (size_t)row * (K_TOTAL / 8) + c16);
        cp_async16(Bbase + sw, Bg + (size_t)row * (K_TOTAL / 8) + c16);
    }
}

// ---------------------------------------------------------------------------
// GEMM + log kernel (dual path)
// ---------------------------------------------------------------------------
__global__ void __launch_bounds__(256, 1)
logmm_gemm_kernel(float* __restrict__ out) {
    extern __shared__ char smem[];
    uint32_t sb = smem_u32(smem);
    int tid = threadIdx.x;
    int wid = tid >> 5;
    int lid = tid & 31;
    int n0 = blockIdx.x * TILE_N;
    int m0 = blockIdx.y * TILE_M;

#if HAS_TCGEN05
    // ======================= tcgen05 path (sm_103a feature set) ============
    if (wid == 0) {
        TCGEN05_ALLOC(sb + SMEM_TMEM, TMEM_COLS);
        TCGEN05_RELINQUISH();
    }
    if (tid == 0) {
        MBARRIER_INIT(sb + SMEM_MBAR0, 1);
        MBARRIER_INIT(sb + SMEM_MBAR1, 1);
    }
    __syncthreads();

    uint32_t tmem;
    asm volatile("ld.shared.b32 %0, [%1];" : "=r"(tmem) : "r"(sb + SMEM_TMEM));

    load_tiles_sts(sb, 0, 0, m0, n0, tid);
    FENCE_PROXY_ASYNC();
    __syncthreads();

    for (int c = 0; c < NCHUNK; c++) {
        int buf = c & 1;
        if (wid == 0) {
            if (elect_one()) {
                uint32_t Abase = sb + SMEM_TILES + buf * BUF_STRIDE;
                uint64_t ad = make_desc(Abase);
                uint64_t bd = make_desc(Abase + TILE_BYTES);
#pragma unroll
                for (int s = 0; s < 4; s++)
                    mma_f16_ss(tmem, ad + s * 2, bd + s * 2, MMA_IDESC, (c > 0) || (s > 0));
                TCGEN05_COMMIT(sb + (buf ? SMEM_MBAR1 : SMEM_MBAR0));
            }
        }
        if (c + 1 < NCHUNK) {
            if (c >= 1) {
                uint32_t mb = sb + (((c + 1) & 1) ? SMEM_MBAR1 : SMEM_MBAR0);
                MBARRIER_WAIT_PARITY(mb, ((c - 1) >> 1) & 1);
            }
            load_tiles_sts(sb, 1 - buf, c + 1, m0, n0, tid);
            FENCE_PROXY_ASYNC();
        }
        __syncthreads();
    }

    MBARRIER_WAIT_PARITY(sb + SMEM_MBAR0, 1);
    MBARRIER_WAIT_PARITY(sb + SMEM_MBAR1, 1);
    TCGEN05_FENCE_AFTER();

    int row = m0 + (wid & 3) * 32 + lid;
    int cbase = (wid >> 2) * 64;
    float* orow = out + (size_t)row * N_TOTAL + n0 + cbase;
#pragma unroll
    for (int half = 0; half < 2; half++) {
        uint32_t d[32];
        LDTM_X32(d, tmem + cbase + half * 32);
        TCGEN05_WAIT_LD();
#pragma unroll
        for (int j = 0; j < 32; j += 4) {
            float4 v;
            v.x = __logf(fmaxf(__uint_as_float(d[j + 0]), 1.17549435e-38f));
            v.y = __logf(fmaxf(__uint_as_float(d[j + 1]), 1.17549435e-38f));
            v.z = __logf(fmaxf(__uint_as_float(d[j + 2]), 1.17549435e-38f));
            v.w = __logf(fmaxf(__uint_as_float(d[j + 3]), 1.17549435e-38f));
            *reinterpret_cast<float4*>(orow + half * 32 + j) = v;
        }
    }
    __syncthreads();
    if (wid == 0) TCGEN05_DEALLOC(tmem, TMEM_COLS);

#else
    // ======================= baseline mma.sync path (plain sm_103) =========
    // 8 warps: warp_m in {0,1} (64 rows each), warp_n in {0..3} (32 cols each)
    int warp_m = wid >> 2;
    int warp_n = wid & 3;

    float acc[4][4][4];
#pragma unroll
    for (int mf = 0; mf < 4; mf++)
#pragma unroll
        for (int nf = 0; nf < 4; nf++)
#pragma unroll
            for (int i = 0; i < 4; i++) acc[mf][nf][i] = 0.0f;

    // Prologue: load chunk 0 into buf 0
    load_tiles_async(sb, 0, 0, m0, n0, tid);
    CP_COMMIT();

    for (int c = 0; c < NCHUNK; c++) {
        int buf = c & 1;
        if (c + 1 < NCHUNK) {
            load_tiles_async(sb, 1 - buf, c + 1, m0, n0, tid);
            CP_COMMIT();
            CP_WAIT(1);          // chunk c's group is complete
        } else {
            CP_WAIT(0);
        }
        __syncthreads();

        uint32_t Ab = sb + SMEM_TILES + buf * BUF_STRIDE;
        uint32_t Bb = Ab + TILE_BYTES;
#pragma unroll
        for (int ks = 0; ks < 4; ks++) {
            uint32_t a[4][4], b[2][4];
#pragma unroll
            for (int mf = 0; mf < 4; mf++) {
                int row = warp_m * 64 + mf * 16 + (lid & 15);
                uint32_t off = (uint32_t)(row * 128 + ks * 32 + ((lid >> 4) << 4));
                ldsm_x4(a[mf], Ab + sw128(off));
            }
#pragma unroll
            for (int p = 0; p < 2; p++) {
                int row = warp_n * 32 + p * 16 + (lid & 7) + ((lid >> 4) << 3);
                uint32_t off = (uint32_t)(row * 128 + ks * 32 + (((lid >> 3) & 1) << 4));
                ldsm_x4(b[p], Bb + sw128(off));
            }
#pragma unroll
            for (int mf = 0; mf < 4; mf++)
#pragma unroll
                for (int nf = 0; nf < 4; nf++)
                    mma16816(acc[mf][nf], a[mf], b[nf >> 1] + (nf & 1) * 2);
        }
        __syncthreads();
    }

    // Epilogue: log + store. Frag layout: c0,c1 at row lid/4, cols (lid%4)*2,+1;
    // c2,c3 at row lid/4+8.
#pragma unroll
    for (int mf = 0; mf < 4; mf++) {
#pragma unroll
        for (int nf = 0; nf < 4; nf++) {
            int row0 = m0 + warp_m * 64 + mf * 16 + (lid >> 2);
            int col = n0 + warp_n * 32 + nf * 8 + (lid & 3) * 2;
            float2 v0, v1;
            v0.x = __logf(fmaxf(acc[mf][nf][0], 1.17549435e-38f));
            v0.y = __logf(fmaxf(acc[mf][nf][1], 1.17549435e-38f));
            v1.x = __logf(fmaxf(acc[mf][nf][2], 1.17549435e-38f));
            v1.y = __logf(fmaxf(acc[mf][nf][3], 1.17549435e-38f));
            *reinterpret_cast<float2*>(out + (size_t)row0 * N_TOTAL + col) = v0;
            *reinterpret_cast<float2*>(out + (size_t)(row0 + 8) * N_TOTAL + col) = v1;
        }
    }
#endif
}

// ---------------------------------------------------------------------------
// Launch
// ---------------------------------------------------------------------------
extern "C" void kernel_launch(void* const* d_in, const int* in_sizes, int n_in,
                              void* d_out, int out_size) {
    const float* x = (const float*)d_in[0];
    const float* mat = (const float*)d_in[1];
    // Defensive: identify by element count (x = 16.7M, matrix = 1.05M)
    if (n_in >= 2 && in_sizes[0] == N_TOTAL * K_TOTAL && in_sizes[1] == M_TOTAL * K_TOTAL) {
        const float* t = x; x = mat; mat = t;
    }
    float* out = (float*)d_out;

    cudaFuncSetAttribute(logmm_gemm_kernel,
                         cudaFuncAttributeMaxDynamicSharedMemorySize, SMEM_TOTAL);

    // 1) x -> bf16
    cvt_x_kernel<<<(M_TOTAL * K_TOTAL) / (256 * 8), 256>>>(x);
    // 2) matrix -> bf16 transposed [N,K]
    cvt_mT_kernel<<<dim3(N_TOTAL / 32, K_TOTAL / 32), dim3(32, 32)>>>(mat);
    // 3) GEMM + log
    dim3 grid(N_TOTAL / TILE_N, M_TOTAL / TILE_M);  // (8, 128)
    logmm_gemm_kernel<<<grid, 256, SMEM_TOTAL>>>(out);
}

// round 3
// speedup vs baseline: 1.0857x; 1.0857x over previous
#include <cuda_runtime.h>
#include <cuda_bf16.h>
#include <cstdint>

// ============================================================================
// LogMM: out[16384,1024] = log( x[16384,1024] @ matrix[1024,1024] )
// (reference's big/small branches sum exactly to log(max(y,tiny)))
//
// Plain sm_103 target (no 'a' feature set in harness PTX) -> baseline-ISA
// bf16 mma.sync (HMMA) pipeline:
//   1) cvt_kernel: fused  x fp32->bf16  AND  matrix[K,N] fp32 -> Bt[N,K] bf16
//   2) gemm: 128x128 tile, BK=64, 3-stage cp.async pipeline, 2 CTAs/SM,
//            one __syncthreads per K-chunk, fused __logf epilogue.
// ============================================================================

#define M_TOTAL 16384
#define N_TOTAL 1024
#define K_TOTAL 1024
#define TILE_M 128
#define TILE_N 128
#define BK 64                    // bf16 per K-chunk (128 B per row)
#define NCHUNK (K_TOTAL / BK)    // 16
#define NSTAGE 3

// SMEM: [0..1024) pad, then 3 buffers of (A tile 16KB + B tile 16KB)
static constexpr int SMEM_TILES = 1024;
static constexpr int TILE_BYTES = TILE_M * 128;     // 16384
static constexpr int BUF_STRIDE = 2 * TILE_BYTES;   // 32768
static constexpr int SMEM_TOTAL = SMEM_TILES + NSTAGE * BUF_STRIDE;  // 99328

// Scratch bf16 buffers (device globals: allocation-free)
__device__ __align__(256) __nv_bfloat16 g_xb[(size_t)M_TOTAL * K_TOTAL];
__device__ __align__(256) __nv_bfloat16 g_bt[(size_t)N_TOTAL * K_TOTAL];

// ---------------------------------------------------------------------------
// Helpers
// ---------------------------------------------------------------------------
__device__ __forceinline__ uint32_t smem_u32(const void* p) {
    uint32_t a;
    asm("{ .reg .u64 t; cvta.to.shared.u64 t, %1; cvt.u32.u64 %0, t; }" : "=r"(a) : "l"(p));
    return a;
}
__device__ __forceinline__ uint32_t sw128(uint32_t off) {
    return off ^ ((off >> 3) & 0x70);
}
__device__ __forceinline__ void cp_async16(uint32_t smem_addr, const void* gptr) {
    asm volatile("cp.async.cg.shared.global [%0], [%1], 16;"
                 :: "r"(smem_addr), "l"(gptr) : "memory");
}
#define CP_COMMIT() asm volatile("cp.async.commit_group;" ::: "memory")
#define CP_WAIT(n)  asm volatile("cp.async.wait_group %0;" :: "n"(n) : "memory")

__device__ __forceinline__ void ldsm_x4(uint32_t* r, uint32_t addr) {
    asm volatile("ldmatrix.sync.aligned.m8n8.x4.shared.b16 {%0, %1, %2, %3}, [%4];"
                 : "=r"(r[0]), "=r"(r[1]), "=r"(r[2]), "=r"(r[3]) : "r"(addr));
}
__device__ __forceinline__ void mma16816(float* c, const uint32_t* a, const uint32_t* b) {
    asm volatile("mma.sync.aligned.m16n8k16.row.col.f32.bf16.bf16.f32 "
                 "{%0, %1, %2, %3}, {%4, %5, %6, %7}, {%8, %9}, {%0, %1, %2, %3};"
                 : "+f"(c[0]), "+f"(c[1]), "+f"(c[2]), "+f"(c[3])
                 : "r"(a[0]), "r"(a[1]), "r"(a[2]), "r"(a[3]), "r"(b[0]), "r"(b[1]));
}
__device__ __forceinline__ uint32_t pack_bf16x2(float a, float b) {
    __nv_bfloat162 h = __floats2bfloat162_rn(a, b);
    return *reinterpret_cast<uint32_t*>(&h);
}

// ---------------------------------------------------------------------------
// Fused conversion kernel:
//   blocks [0, 8192):         x fp32 -> g_xb bf16 (8 elems/thread)
//   blocks [8192, 8192+1024): matrix[K,N] -> g_bt[N,K] bf16 (32x32 tiles)
// ---------------------------------------------------------------------------
#define CVT_X_BLOCKS (M_TOTAL * K_TOTAL / (256 * 8))   // 8192
#define CVT_T_BLOCKS ((K_TOTAL / 32) * (N_TOTAL / 32)) // 1024

__global__ void __launch_bounds__(256)
cvt_kernel(const float* __restrict__ x, const float* __restrict__ m) {
    int tid = threadIdx.x;
    if (blockIdx.x < CVT_X_BLOCKS) {
        size_t i = ((size_t)blockIdx.x * 256 + tid) * 8;
        float4 a = *reinterpret_cast<const float4*>(x + i);
        float4 b = *reinterpret_cast<const float4*>(x + i + 4);
        uint4 o;
        o.x = pack_bf16x2(a.x, a.y);
        o.y = pack_bf16x2(a.z, a.w);
        o.z = pack_bf16x2(b.x, b.y);
        o.w = pack_bf16x2(b.z, b.w);
        *reinterpret_cast<uint4*>(g_xb + i) = o;
    } else {
        __shared__ float tile[32][33];
        int t = blockIdx.x - CVT_X_BLOCKS;
        int bn = (t & 31) * 32;          // n block
        int bk = (t >> 5) * 32;          // k block
        int lane = tid & 31;
        int rr = tid >> 5;               // 0..7
#pragma unroll
        for (int i = 0; i < 4; i++) {
            int row = i * 8 + rr;        // k within tile
            tile[row][lane] = m[(size_t)(bk + row) * N_TOTAL + bn + lane];
        }
        __syncthreads();
#pragma unroll
        for (int i = 0; i < 4; i++) {
            int row = i * 8 + rr;        // n within tile
            g_bt[(size_t)(bn + row) * K_TOTAL + bk + lane] =
                __float2bfloat16_rn(tile[lane][row]);
        }
    }
}

// ---------------------------------------------------------------------------
// GEMM + log kernel
// ---------------------------------------------------------------------------
__device__ __forceinline__ void load_tiles_async(uint32_t smem_base, int buf, int kc,
                                                 int m0, int n0, int tid) {
    const uint4* Ag = reinterpret_cast<const uint4*>(g_xb + (size_t)m0 * K_TOTAL + kc * BK);
    const uint4* Bg = reinterpret_cast<const uint4*>(g_bt + (size_t)n0 * K_TOTAL + kc * BK);
    uint32_t Abase = smem_base + SMEM_TILES + buf * BUF_STRIDE;
    uint32_t Bbase = Abase + TILE_BYTES;
#pragma unroll
    for (int i = 0; i < 4; i++) {
        int cc = i * 256 + tid;           // 1024 16B-chunks per tile
        int row = cc >> 3;                // 0..127
        int c16 = cc & 7;                 // 16B chunk within 128B row
        uint32_t sw = sw128((uint32_t)(row * 128 + c16 * 16));
        cp_async16(Abase + sw, Ag + (size_t)row * (K_TOTAL / 8) + c16);
        cp_async16(Bbase + sw, Bg + (size_t)row * (K_TOTAL / 8) + c16);
    }
}

__global__ void __launch_bounds__(256, 2)
logmm_gemm_kernel(float* __restrict__ out) {
    extern __shared__ char smem[];
    uint32_t sb = smem_u32(smem);
    int tid = threadIdx.x;
    int wid = tid >> 5;
    int lid = tid & 31;
    int n0 = blockIdx.x * TILE_N;
    int m0 = blockIdx.y * TILE_M;

    // 8 warps: warp_m in {0,1} (64 rows), warp_n in {0..3} (32 cols)
    int warp_m = wid >> 2;
    int warp_n = wid & 3;

    float acc[4][4][4];
#pragma unroll
    for (int mf = 0; mf < 4; mf++)
#pragma unroll
        for (int nf = 0; nf < 4; nf++)
#pragma unroll
            for (int i = 0; i < 4; i++) acc[mf][nf][i] = 0.0f;

    // Prologue: fill 2 of 3 stages
    load_tiles_async(sb, 0, 0, m0, n0, tid);
    CP_COMMIT();
    load_tiles_async(sb, 1, 1, m0, n0, tid);
    CP_COMMIT();

    for (int c = 0; c < NCHUNK; c++) {
        if (c == NCHUNK - 1) { CP_WAIT(0); } else { CP_WAIT(1); }
        __syncthreads();

        // Prefetch chunk c+2 into buffer (c+2)%3 (safe: everyone is past chunk c-1)
        if (c + 2 < NCHUNK) {
            load_tiles_async(sb, (c + 2) % NSTAGE, c + 2, m0, n0, tid);
            CP_COMMIT();
        }

        uint32_t Ab = sb + SMEM_TILES + (c % NSTAGE) * BUF_STRIDE;
        uint32_t Bb = Ab + TILE_BYTES;
#pragma unroll
        for (int ks = 0; ks < 4; ks++) {
            uint32_t a[4][4], b[2][4];
#pragma unroll
            for (int mf = 0; mf < 4; mf++) {
                int row = warp_m * 64 + mf * 16 + (lid & 15);
                uint32_t off = (uint32_t)(row * 128 + ks * 32 + ((lid >> 4) << 4));
                ldsm_x4(a[mf], Ab + sw128(off));
            }
#pragma unroll
            for (int p = 0; p < 2; p++) {
                int row = warp_n * 32 + p * 16 + (lid & 7) + ((lid >> 4) << 3);
                uint32_t off = (uint32_t)(row * 128 + ks * 32 + (((lid >> 3) & 1) << 4));
                ldsm_x4(b[p], Bb + sw128(off));
            }
#pragma unroll
            for (int mf = 0; mf < 4; mf++)
#pragma unroll
                for (int nf = 0; nf < 4; nf++)
                    mma16816(acc[mf][nf], a[mf], b[nf >> 1] + (nf & 1) * 2);
        }
    }

    // Epilogue: log + store. Frag: c0,c1 at row lid/4, cols (lid%4)*2,+1;
    // c2,c3 at row lid/4 + 8.
#pragma unroll
    for (int mf = 0; mf < 4; mf++) {
#pragma unroll
        for (int nf = 0; nf < 4; nf++) {
            int row0 = m0 + warp_m * 64 + mf * 16 + (lid >> 2);
            int col = n0 + warp_n * 32 + nf * 8 + (lid & 3) * 2;
            float2 v0, v1;
            v0.x = __logf(fmaxf(acc[mf][nf][0], 1.17549435e-38f));
            v0.y = __logf(fmaxf(acc[mf][nf][1], 1.17549435e-38f));
            v1.x = __logf(fmaxf(acc[mf][nf][2], 1.17549435e-38f));
            v1.y = __logf(fmaxf(acc[mf][nf][3], 1.17549435e-38f));
            *reinterpret_cast<float2*>(out + (size_t)row0 * N_TOTAL + col) = v0;
            *reinterpret_cast<float2*>(out + (size_t)(row0 + 8) * N_TOTAL + col) = v1;
        }
    }
}

// ---------------------------------------------------------------------------
// Launch
// ---------------------------------------------------------------------------
extern "C" void kernel_launch(void* const* d_in, const int* in_sizes, int n_in,
                              void* d_out, int out_size) {
    const float* x = (const float*)d_in[0];
    const float* mat = (const float*)d_in[1];
    if (n_in >= 2 && in_sizes[0] == N_TOTAL * K_TOTAL && in_sizes[1] == M_TOTAL * K_TOTAL) {
        const float* t = x; x = mat; mat = t;
    }
    float* out = (float*)d_out;

    cudaFuncSetAttribute(logmm_gemm_kernel,
                         cudaFuncAttributeMaxDynamicSharedMemorySize, SMEM_TOTAL);

    cvt_kernel<<<CVT_X_BLOCKS + CVT_T_BLOCKS, 256>>>(x, mat);
    dim3 grid(N_TOTAL / TILE_N, M_TOTAL / TILE_M);  // (8, 128)
    logmm_gemm_kernel<<<grid, 256, SMEM_TOTAL>>>(out);
}